// round 5
// baseline (speedup 1.0000x reference)
#include <cuda_runtime.h>
#include <cstdint>

#define NB   4
#define IC   3
#define OC   16
#define ODIM 127
#define H_STR   128
#define D_STR   (128*128)
#define C_STR   (128*128*128)
#define O_HSTR  127
#define O_DSTR  (127*127)
#define O_CSTR  (127*127*127)

typedef unsigned long long ull;

// Weight pairs: [ic][kh][kd][oc] -> float2 (w_kw0, w_kw1)
__device__ float2 g_w2[3][2][2][16];
__device__ float2 g_fb[16];            // (bias, 0)

__device__ __forceinline__ ull fma2(ull a, ull b, ull c) {
    ull d;
    asm("fma.rn.f32x2 %0, %1, %2, %3;" : "=l"(d) : "l"(a), "l"(b), "l"(c));
    return d;
}
__device__ __forceinline__ ull pack2(float lo, float hi) {
    ull d;
    asm("mov.b64 %0, {%1, %2};" : "=l"(d) : "f"(lo), "f"(hi));
    return d;
}
__device__ __forceinline__ float2 unpack2(ull v) {
    float2 r;
    asm("mov.b64 {%0, %1}, %2;" : "=f"(r.x), "=f"(r.y) : "l"(v));
    return r;
}

// Fold ConvTranspose(k3,s2,p1)+AvgPool(2) -> 2x2x2 conv, with scales.
__global__ void prep_kernel(const float* __restrict__ cw,
                            const float* __restrict__ cb,
                            const float* __restrict__ eb) {
    int t = threadIdx.x;
    if (t >= 192) return;
    // t -> (ic, kh, kd, oc)
    int oc = t & 15;
    int kd = (t >> 4) & 1;
    int kh = (t >> 5) & 1;
    int ic = t >> 6;

    const float* w = cw + (ic * 16 + oc) * 27;   // (ic, oc, 3,3,3)
    float s[2];
#pragma unroll
    for (int kw = 0; kw < 2; kw++) {
        int dlo = kd ? 0 : 1, dhi = kd ? 1 : 3;
        int hlo = kh ? 0 : 1, hhi = kh ? 1 : 3;
        int wlo = kw ? 0 : 1, whi = kw ? 1 : 3;
        float acc = 0.f;
        for (int i = dlo; i < dhi; i++)
            for (int j = hlo; j < hhi; j++)
                for (int k = wlo; k < whi; k++)
                    acc += w[i * 9 + j * 3 + k];
        s[kw] = acc * 0.0625f;                   // SCALE1*SCALE2*0.125
    }
    g_w2[ic][kh][kd][oc] = make_float2(s[0], s[1]);
    if (t < 16) {
        float b = cb[t] * 0.5f + eb[t];
        g_fb[t] = make_float2(b, 0.f);           // acc init: (bias, 0)
    }
}

// kw-paired accumulation: acc(w) = (bias + sum w0*x(w), sum w1*x(w+1));
// out(w) = acc.lo + acc.hi.  Thread owns w = 64c + 2*lane + parity,
// c in {0,1}, parity in {0,1} -> 4 outputs per oc. 16 oc in 2 passes of 8.
// Block = 32(lane) x 8(oh). Grid = (16 oh-tiles, 127 od, 4 n).
__global__ void __launch_bounds__(256, 2)
conv_main(const float* __restrict__ x, float* __restrict__ out) {
    __shared__ float2 smw[3][2][2][16];
    __shared__ float2 smb[16];

    int tid = threadIdx.y * 32 + threadIdx.x;
    {
        const float2* gw = (const float2*)g_w2;
        float2* sw = (float2*)smw;
        if (tid < 192) sw[tid] = gw[tid];
        if (tid < 16) smb[tid] = g_fb[tid];
    }
    __syncthreads();

    int lane = threadIdx.x;
    int oh = blockIdx.x * 8 + threadIdx.y;
    if (oh >= ODIM) return;
    int od = blockIdx.y;
    int n  = blockIdx.z;
    bool lastlane = (lane == 31);

    const float* xb = x + (size_t)n * IC * C_STR
                        + (size_t)od * D_STR
                        + (size_t)oh * H_STR + 2 * lane;
    float* ob = out + (size_t)n * OC * O_CSTR
                    + (size_t)od * O_DSTR
                    + (size_t)oh * O_HSTR + 2 * lane;

#pragma unroll 1
    for (int half = 0; half < 2; half++) {
        // acc[s][oc]: s = 2*c + parity  (c = w-chunk of 64, parity = w&1)
        ull acc[4][8];
#pragma unroll
        for (int oc = 0; oc < 8; oc++) {
            ull b = *(const ull*)&smb[half * 8 + oc];
            acc[0][oc] = b; acc[1][oc] = b; acc[2][oc] = b; acc[3][oc] = b;
        }

#pragma unroll
        for (int ic = 0; ic < IC; ic++) {
#pragma unroll
            for (int kh = 0; kh < 2; kh++) {
                const float* rp = xb + (size_t)ic * C_STR + (size_t)kh * H_STR;
                ull X[2][4];   // [kd][s]
#pragma unroll
                for (int kd = 0; kd < 2; kd++) {
                    const float* row = rp + (size_t)kd * D_STR;
                    float2 p0 = *(const float2*)(row);        // x[2L],    x[2L+1]
                    float2 p1 = *(const float2*)(row + 64);   // x[64+2L], x[64+2L+1]
                    // x[w+1] for odd w: next even pair's .x (cross-lane)
                    float u0 = __shfl_down_sync(0xffffffffu, p0.x, 1);
                    float u1 = __shfl_down_sync(0xffffffffu, p1.x, 1); // lane31: w=127 invalid
                    float b0 = __shfl_sync(0xffffffffu, p1.x, 0);
                    if (lastlane) u0 = b0;   // w=63 needs x[64] = chunk1 lane0
                    X[kd][0] = pack2(p0.x, p0.y);
                    X[kd][1] = pack2(p0.y, u0);
                    X[kd][2] = pack2(p1.x, p1.y);
                    X[kd][3] = pack2(p1.y, u1);
                }
#pragma unroll
                for (int kd = 0; kd < 2; kd++) {
#pragma unroll
                    for (int oc = 0; oc < 8; oc++) {
                        ull W = *(const ull*)&smw[ic][kh][kd][half * 8 + oc];
                        acc[0][oc] = fma2(X[kd][0], W, acc[0][oc]);
                        acc[1][oc] = fma2(X[kd][1], W, acc[1][oc]);
                        acc[2][oc] = fma2(X[kd][2], W, acc[2][oc]);
                        acc[3][oc] = fma2(X[kd][3], W, acc[3][oc]);
                    }
                }
            }
        }

#pragma unroll
        for (int oc = 0; oc < 8; oc++) {
            float* o = ob + (size_t)(half * 8 + oc) * O_CSTR;
            float2 a0 = unpack2(acc[0][oc]);
            float2 a1 = unpack2(acc[1][oc]);
            float2 a2 = unpack2(acc[2][oc]);
            float2 a3 = unpack2(acc[3][oc]);
            __stcs(o,      a0.x + a0.y);          // w = 2L
            __stcs(o + 1,  a1.x + a1.y);          // w = 2L+1
            __stcs(o + 64, a2.x + a2.y);          // w = 64+2L
            if (!lastlane)
                __stcs(o + 65, a3.x + a3.y);      // w = 64+2L+1 (127 invalid)
        }
    }
}

extern "C" void kernel_launch(void* const* d_in, const int* in_sizes, int n_in,
                              void* d_out, int out_size) {
    const float* x  = (const float*)d_in[0];
    const float* cw = (const float*)d_in[1];
    const float* cb = (const float*)d_in[2];
    const float* eb = (const float*)d_in[3];
    float* out = (float*)d_out;

    prep_kernel<<<1, 192>>>(cw, cb, eb);

    dim3 block(32, 8, 1);
    dim3 grid(16, ODIM, NB);    // 16 oh-tiles, 127 od, 4 batches
    conv_main<<<grid, block>>>(x, out);
}

// round 12
// speedup vs baseline: 1.1689x; 1.1689x over previous
#include <cuda_runtime.h>
#include <cstdint>

#define NB   4
#define IC   3
#define OC   16
#define ODIM 127
#define H_STR   128
#define D_STR   (128*128)
#define C_STR   (128*128*128)
#define O_HSTR  127
#define O_DSTR  (127*127)
#define O_CSTR  (127*127*127)

typedef unsigned long long ull;

// Folded weights, scalar layout: [ic][kh][kd][kw][oc]
__device__ float g_wS[3][2][2][2][16];
__device__ float g_fbS[16];

__device__ __forceinline__ ull fma2(ull a, ull b, ull c) {
    ull d;
    asm("fma.rn.f32x2 %0, %1, %2, %3;" : "=l"(d) : "l"(a), "l"(b), "l"(c));
    return d;
}
__device__ __forceinline__ ull pack2(float lo, float hi) {
    ull d;
    asm("mov.b64 %0, {%1, %2};" : "=l"(d) : "f"(lo), "f"(hi));
    return d;
}
__device__ __forceinline__ float2 unpack2(ull v) {
    float2 r;
    asm("mov.b64 {%0, %1}, %2;" : "=f"(r.x), "=f"(r.y) : "l"(v));
    return r;
}

// Fold ConvTranspose(k3,s2,p1)+AvgPool(2) -> 2x2x2 conv, with scales.
__global__ void prep_kernel(const float* __restrict__ cw,
                            const float* __restrict__ cb,
                            const float* __restrict__ eb) {
    int t = threadIdx.x;
    if (t >= 384) return;
    int oc = t & 15;
    int kw = (t >> 4) & 1;
    int kd = (t >> 5) & 1;
    int kh = (t >> 6) & 1;
    int ic = t >> 7;                              // 0..2

    int dlo = kd ? 0 : 1, dhi = kd ? 1 : 3;
    int hlo = kh ? 0 : 1, hhi = kh ? 1 : 3;
    int wlo = kw ? 0 : 1, whi = kw ? 1 : 3;
    const float* w = cw + (ic * 16 + oc) * 27;    // (ic, oc, 3,3,3)
    float s = 0.f;
    for (int i = dlo; i < dhi; i++)
        for (int j = hlo; j < hhi; j++)
            for (int k = wlo; k < whi; k++)
                s += w[i * 9 + j * 3 + k];
    g_wS[ic][kh][kd][kw][oc] = s * 0.0625f;       // SCALE1*SCALE2*0.125
    if (t < 16)
        g_fbS[t] = cb[t] * 0.5f + eb[t];          // (cb*SCALE1 + ext)*SCALE2
}

// Single pass: 1 od x 16 oc (8 oc-pairs as fma2 lanes) x 2 w-slots
// (w = wbase + lane + {0,32}).  acc[ws][p] = (out_oc2p, out_oc2p+1).
// Weights consumed as natural adjacent-oc pairs from SMEM (LDS.128);
// x scalars duplicated with 1 MOV each.
// Block = 32(lane) x 8(oh). Grid.x = wt*16 + ohtile, y = od, z = n.
__global__ void __launch_bounds__(256, 3)
conv_main(const float* __restrict__ x, float* __restrict__ out) {
    __shared__ __align__(16) float smw[3][2][2][2][16];
    __shared__ __align__(8)  float smb[16];

    int tid = threadIdx.y * 32 + threadIdx.x;
    {
        const float* gw = (const float*)g_wS;
        float* sw = (float*)smw;
        for (int i = tid; i < 384; i += 256) sw[i] = gw[i];   // FIX: full copy
        if (tid < 16) smb[tid] = g_fbS[tid];
    }
    __syncthreads();

    int lane = threadIdx.x;
    int wt = blockIdx.x >> 4;                 // 0 or 1
    int oh = (blockIdx.x & 15) * 8 + threadIdx.y;
    if (oh >= ODIM) return;
    int od = blockIdx.y;
    int n  = blockIdx.z;
    int wbase = wt * 64;
    bool lastlane = (lane == 31);

    const float* xb = x + (size_t)n * IC * C_STR
                        + (size_t)od * D_STR
                        + (size_t)oh * H_STR + wbase + lane;
    float* ob = out + (size_t)n * OC * O_CSTR
                    + (size_t)od * O_DSTR
                    + (size_t)oh * O_HSTR + wbase + lane;

    // acc[ws][p]: ws = w-slot (lane / lane+32), p = oc pair (2p, 2p+1)
    ull acc[2][8];
#pragma unroll
    for (int p = 0; p < 8; p++) {
        ull b = *(const ull*)&smb[2 * p];
        acc[0][p] = b;
        acc[1][p] = b;
    }

#pragma unroll
    for (int ic = 0; ic < IC; ic++) {
#pragma unroll
        for (int kh = 0; kh < 2; kh++) {
            const float* rp = xb + (size_t)ic * C_STR + (size_t)kh * H_STR;
#pragma unroll
            for (int kd = 0; kd < 2; kd++) {
                const float* row = rp + (size_t)kd * D_STR;
                float v0 = row[0];                 // x[wbase+lane]
                float v1 = row[32];                // x[wbase+lane+32]
                float u0 = __shfl_down_sync(0xffffffffu, v0, 1);
                float u1 = __shfl_down_sync(0xffffffffu, v1, 1);
                float b0 = __shfl_sync(0xffffffffu, v1, 0);  // x[wbase+32]
                // lane31 ws1 needs x[wbase+64]; only valid/needed for wt==0
                float e = (lastlane && wt == 0) ? row[33] : 0.f;
                if (lastlane) { u0 = b0; u1 = e; }

                ull A0 = pack2(v0, v0);            // kw=0 operand, ws0
                ull A1 = pack2(v1, v1);            // kw=0 operand, ws1
                ull B0 = pack2(u0, u0);            // kw=1 operand, ws0
                ull B1 = pack2(u1, u1);            // kw=1 operand, ws1

                const ulonglong2* W0 =
                    (const ulonglong2*)&smw[ic][kh][kd][0][0];
                const ulonglong2* W1 =
                    (const ulonglong2*)&smw[ic][kh][kd][1][0];
#pragma unroll
                for (int q = 0; q < 4; q++) {
                    ulonglong2 w0 = W0[q];         // oc pairs 2q, 2q+1 (kw=0)
                    acc[0][2*q]   = fma2(A0, w0.x, acc[0][2*q]);
                    acc[1][2*q]   = fma2(A1, w0.x, acc[1][2*q]);
                    acc[0][2*q+1] = fma2(A0, w0.y, acc[0][2*q+1]);
                    acc[1][2*q+1] = fma2(A1, w0.y, acc[1][2*q+1]);
                }
#pragma unroll
                for (int q = 0; q < 4; q++) {
                    ulonglong2 w1 = W1[q];         // oc pairs (kw=1)
                    acc[0][2*q]   = fma2(B0, w1.x, acc[0][2*q]);
                    acc[1][2*q]   = fma2(B1, w1.x, acc[1][2*q]);
                    acc[0][2*q+1] = fma2(B0, w1.y, acc[0][2*q+1]);
                    acc[1][2*q+1] = fma2(B1, w1.y, acc[1][2*q+1]);
                }
            }
        }
    }

    // ws0 outputs (w = wbase+lane) always valid.
    // ws1 (w = wbase+lane+32): invalid only for wt==1, lane31 (w=127).
    bool skiplast = lastlane && (wt == 1);
#pragma unroll
    for (int p = 0; p < 8; p++) {
        float* oa  = ob + (size_t)(2 * p) * O_CSTR;
        float* obp = ob + (size_t)(2 * p + 1) * O_CSTR;
        float2 a0 = unpack2(acc[0][p]);
        float2 a1 = unpack2(acc[1][p]);
        __stcs(oa,  a0.x);
        __stcs(obp, a0.y);
        if (!skiplast) {
            __stcs(oa + 32,  a1.x);
            __stcs(obp + 32, a1.y);
        }
    }
}

extern "C" void kernel_launch(void* const* d_in, const int* in_sizes, int n_in,
                              void* d_out, int out_size) {
    const float* x  = (const float*)d_in[0];
    const float* cw = (const float*)d_in[1];
    const float* cb = (const float*)d_in[2];
    const float* eb = (const float*)d_in[3];
    float* out = (float*)d_out;

    prep_kernel<<<1, 384>>>(cw, cb, eb);

    dim3 block(32, 8, 1);
    dim3 grid(32, ODIM, NB);    // x: 2 w-tiles * 16 oh-tiles, y: od, z: n
    conv_main<<<grid, block>>>(x, out);
}